// round 3
// baseline (speedup 1.0000x reference)
#include <cuda_runtime.h>
#include <math.h>

// Problem constants
#define B_TOT 8192
#define T_STEPS 90
#define F_IN 7
#define H 128
#define G4 512      // 4*H
#define D1C 128
#define D2C 64
#define NOUT 30
#define NB 64       // batch rows per CTA
#define NCTA (B_TOT / NB)   // 128
#define NTHR 256

// ---------------------------------------------------------------------------
// Scratch: k-major transposed weights + fused biases (written by prep kernel
// each launch; __device__ globals to satisfy the no-alloc rule).
// ---------------------------------------------------------------------------
__device__ float g_Wt0[2 * H * G4];   // [k=256][j=512]: k<128 -> Wih0, else Whh0
__device__ float g_Wt1[2 * H * G4];
__device__ float g_Wd1t[H * D1C];     // [k=128][d=128]
__device__ float g_Wd2t[D1C * D2C];   // [k=128][d=64]
__device__ float g_bias0[G4];
__device__ float g_bias1[G4];

__global__ void prep_kernel(const float* __restrict__ Wih0, const float* __restrict__ Whh0,
                            const float* __restrict__ bih0, const float* __restrict__ bhh0,
                            const float* __restrict__ Wih1, const float* __restrict__ Whh1,
                            const float* __restrict__ bih1, const float* __restrict__ bhh1,
                            const float* __restrict__ Wd1,  const float* __restrict__ Wd2)
{
    int idx = blockIdx.x * blockDim.x + threadIdx.x;
    int stride = gridDim.x * blockDim.x;
    for (int i = idx; i < 2 * H * G4; i += stride) {
        int k = i / G4, j = i % G4;
        g_Wt0[i] = (k < H) ? Wih0[j * H + k] : Whh0[j * H + (k - H)];
        g_Wt1[i] = (k < H) ? Wih1[j * H + k] : Whh1[j * H + (k - H)];
    }
    for (int i = idx; i < H * D1C; i += stride) {
        int k = i / D1C, d = i % D1C;
        g_Wd1t[i] = Wd1[d * H + k];
    }
    for (int i = idx; i < D1C * D2C; i += stride) {
        int k = i / D2C, d = i % D2C;
        g_Wd2t[i] = Wd2[d * D1C + k];
    }
    for (int i = idx; i < G4; i += stride) {
        g_bias0[i] = bih0[i] + bhh0[i];
        g_bias1[i] = bih1[i] + bhh1[i];
    }
}

// ---------------------------------------------------------------------------
// f32x2 helpers (FFMA2 path — only reachable through PTX)
// ---------------------------------------------------------------------------
__device__ __forceinline__ unsigned long long splat2(float v) {
    unsigned long long r;
    asm("mov.b64 %0, {%1, %1};" : "=l"(r) : "f"(v));
    return r;
}
__device__ __forceinline__ unsigned long long pack2(float lo, float hi) {
    unsigned long long r;
    asm("mov.b64 %0, {%1, %2};" : "=l"(r) : "f"(lo), "f"(hi));
    return r;
}
__device__ __forceinline__ void unpack2(unsigned long long v, float& lo, float& hi) {
    asm("mov.b64 {%0, %1}, %2;" : "=f"(lo), "=f"(hi) : "l"(v));
}
__device__ __forceinline__ void ffma2(unsigned long long& d,
                                      unsigned long long a, unsigned long long b) {
    asm("fma.rn.f32x2 %0, %1, %2, %0;" : "+l"(d) : "l"(a), "l"(b));
}

__device__ __forceinline__ float sigf(float x) {
    return __fdividef(1.f, 1.f + __expf(-x));
}
__device__ __forceinline__ float tanh_fast(float x) {
    // tanh(x) = 2*sigmoid(2x) - 1
    return 2.f * sigf(2.f * x) - 1.f;
}

// One 128-k half of the gate GEMM. Wt: global k-major [128][512] (pre-offset),
// A: smem [128][64]. Accumulators packed over h-pairs.
__device__ __forceinline__ void gemm128(const float* __restrict__ Wt,
                                        const float* __restrict__ A,
                                        int h4, int b8,
                                        unsigned long long acc[4][2][8])
{
#pragma unroll 2
    for (int k = 0; k < H; ++k) {
        const float* wr = Wt + k * G4 + h4;
        ulonglong2 w0 = *reinterpret_cast<const ulonglong2*>(wr);
        ulonglong2 w1 = *reinterpret_cast<const ulonglong2*>(wr + 128);
        ulonglong2 w2 = *reinterpret_cast<const ulonglong2*>(wr + 256);
        ulonglong2 w3 = *reinterpret_cast<const ulonglong2*>(wr + 384);
        const float4* ar = reinterpret_cast<const float4*>(A + k * NB + b8);
        float4 a0 = ar[0];
        float4 a1 = ar[1];
        unsigned long long s[8];
        s[0] = splat2(a0.x); s[1] = splat2(a0.y); s[2] = splat2(a0.z); s[3] = splat2(a0.w);
        s[4] = splat2(a1.x); s[5] = splat2(a1.y); s[6] = splat2(a1.z); s[7] = splat2(a1.w);
#pragma unroll
        for (int b = 0; b < 8; ++b) {
            unsigned long long sv = s[b];
            ffma2(acc[0][0][b], w0.x, sv); ffma2(acc[0][1][b], w0.y, sv);
            ffma2(acc[1][0][b], w1.x, sv); ffma2(acc[1][1][b], w1.y, sv);
            ffma2(acc[2][0][b], w2.x, sv); ffma2(acc[2][1][b], w2.y, sv);
            ffma2(acc[3][0][b], w3.x, sv); ffma2(acc[3][1][b], w3.y, sv);
        }
    }
}

__device__ __forceinline__ void init_acc(unsigned long long acc[4][2][8],
                                         const float* __restrict__ bias, int h4)
{
#pragma unroll
    for (int g = 0; g < 4; ++g)
#pragma unroll
        for (int p = 0; p < 2; ++p) {
            unsigned long long bi = pack2(bias[g * H + h4 + 2 * p],
                                          bias[g * H + h4 + 2 * p + 1]);
#pragma unroll
            for (int b = 0; b < 8; ++b) acc[g][p][b] = bi;
        }
}

// Gate pointwise: c' = sig(f)*c + sig(i)*tanh(g); h = sig(o)*tanh(c')
__device__ __forceinline__ void pointwise(unsigned long long acc[4][2][8],
                                          float* __restrict__ cbuf,
                                          float* __restrict__ hbuf,
                                          int h4, int b8)
{
#pragma unroll
    for (int p = 0; p < 2; ++p) {
        int idx0 = (h4 + 2 * p) * NB + b8;
#pragma unroll
        for (int b = 0; b < 8; ++b) {
            float i0, i1, f0, f1, gg0, gg1, o0, o1;
            unpack2(acc[0][p][b], i0, i1);
            unpack2(acc[1][p][b], f0, f1);
            unpack2(acc[2][p][b], gg0, gg1);
            unpack2(acc[3][p][b], o0, o1);
            int idx = idx0 + b;
            float cp0 = cbuf[idx], cp1 = cbuf[idx + NB];
            float cn0 = sigf(f0) * cp0 + sigf(i0) * tanh_fast(gg0);
            float cn1 = sigf(f1) * cp1 + sigf(i1) * tanh_fast(gg1);
            cbuf[idx]      = cn0;
            cbuf[idx + NB] = cn1;
            hbuf[idx]      = sigf(o0) * tanh_fast(cn0);
            hbuf[idx + NB] = sigf(o1) * tanh_fast(cn1);
        }
    }
}

// SMEM layout (floats)
#define SM_XH    0          // [128][64]
#define SM_H0    8192
#define SM_H1    16384
#define SM_C0    24576
#define SM_C1    32768
#define SM_XROW  40960      // [64][8]
#define SM_WIN   41472      // [128][8]
#define SM_B0    42496      // [512]
#define SM_B1    43008      // [512]
#define SM_GIN   43520
#define SM_BEIN  43648
#define SM_GLN   43776
#define SM_BELN  43904
#define SM_TOTAL 44032      // floats -> 176128 bytes

__global__ void __launch_bounds__(NTHR, 1)
lstm_kernel(const float* __restrict__ x,
            const float* __restrict__ W_in, const float* __restrict__ b_in,
            const float* __restrict__ g_in, const float* __restrict__ be_in,
            const float* __restrict__ g_ln, const float* __restrict__ be_ln,
            const float* __restrict__ b_d1, const float* __restrict__ b_d2,
            const float* __restrict__ W_d3, const float* __restrict__ b_d3,
            float* __restrict__ out)
{
    extern __shared__ float sm[];
    float* xh   = sm + SM_XH;
    float* h0   = sm + SM_H0;
    float* h1   = sm + SM_H1;
    float* c0   = sm + SM_C0;
    float* c1   = sm + SM_C1;
    float* xrow = sm + SM_XROW;
    float* Wins = sm + SM_WIN;
    float* b0s  = sm + SM_B0;
    float* b1s  = sm + SM_B1;
    float* gins = sm + SM_GIN;
    float* beins= sm + SM_BEIN;
    float* glns = sm + SM_GLN;
    float* belns= sm + SM_BELN;

    const int tid   = threadIdx.x;
    const int cta   = blockIdx.x;
    const int bbase = cta * NB;

    // prologue: zero state, stage constants
    for (int i = tid; i < 32768; i += NTHR) sm[SM_H0 + i] = 0.f;   // h0,h1,c0,c1
    for (int i = tid; i < H * F_IN; i += NTHR) {
        int h = i / F_IN, f = i % F_IN;
        Wins[h * 8 + f] = W_in[i];
    }
    for (int i = tid; i < G4; i += NTHR) { b0s[i] = g_bias0[i]; b1s[i] = g_bias1[i]; }
    for (int i = tid; i < H; i += NTHR) {
        gins[i] = g_in[i]; beins[i] = be_in[i]; glns[i] = g_ln[i]; belns[i] = be_ln[i];
    }
    __syncthreads();

    const int h4 = (tid >> 3) * 4;   // hidden-tile base (0..124)
    const int b8 = (tid & 7) * 8;    // batch-tile base  (0..56)

    unsigned long long acc[4][2][8];

    for (int t = 0; t < T_STEPS; ++t) {
        // ---- input rows ----
        if (tid < NB) {
            const float* xr = x + ((long long)(bbase + tid) * T_STEPS + t) * F_IN;
#pragma unroll
            for (int f = 0; f < F_IN; ++f) xrow[tid * 8 + f] = xr[f];
        }
        __syncthreads();

        // ---- input projection: xh_raw[h][b] ----
        {
            int h  = tid >> 1;
            int bo = (tid & 1) * 32;
            float w[F_IN];
#pragma unroll
            for (int f = 0; f < F_IN; ++f) w[f] = Wins[h * 8 + f];
            float bi = b_in[h];
            for (int j = 0; j < 32; ++j) {
                int b = bo + j;
                float s = bi;
#pragma unroll
                for (int f = 0; f < F_IN; ++f) s += w[f] * xrow[b * 8 + f];
                xh[h * NB + b] = s;
            }
        }
        __syncthreads();

        // ---- LayerNorm over h (per batch row) ----
        if (tid < NB) {
            int b = tid;
            float s = 0.f, ss = 0.f;
            for (int h = 0; h < H; ++h) {
                float v = xh[h * NB + b];
                s += v; ss += v * v;
            }
            float mu = s * (1.f / H);
            float var = ss * (1.f / H) - mu * mu;
            float rs = rsqrtf(var + 1e-5f);
            for (int h = 0; h < H; ++h) {
                float v = xh[h * NB + b];
                xh[h * NB + b] = (v - mu) * rs * gins[h] + beins[h];
            }
        }
        __syncthreads();

        // ---- LSTM layer 0 ----
        init_acc(acc, b0s, h4);
        gemm128(g_Wt0,          xh, h4, b8, acc);
        gemm128(g_Wt0 + H * G4, h0, h4, b8, acc);
        __syncthreads();                       // all reads of h0 done
        pointwise(acc, c0, h0, h4, b8);
        __syncthreads();

        // ---- LSTM layer 1 ----
        init_acc(acc, b1s, h4);
        gemm128(g_Wt1,          h0, h4, b8, acc);
        gemm128(g_Wt1 + H * G4, h1, h4, b8, acc);
        __syncthreads();
        pointwise(acc, c1, h1, h4, b8);
        __syncthreads();
    }

    // ---- final LayerNorm on h1 -> xh ----
    if (tid < NB) {
        int b = tid;
        float s = 0.f, ss = 0.f;
        for (int h = 0; h < H; ++h) {
            float v = h1[h * NB + b];
            s += v; ss += v * v;
        }
        float mu = s * (1.f / H);
        float rs = rsqrtf(ss * (1.f / H) - mu * mu + 1e-5f);
        for (int h = 0; h < H; ++h) {
            float v = h1[h * NB + b];
            xh[h * NB + b] = (v - mu) * rs * glns[h] + belns[h];
        }
    }
    __syncthreads();

    // ---- dense1: [128] <- relu(xh @ Wd1t + b_d1) -> h0 ----
    {
        int d4 = (tid >> 3) * 4;
        int bb = (tid & 7) * 8;
        float a[4][8];
#pragma unroll
        for (int d = 0; d < 4; ++d)
#pragma unroll
            for (int b = 0; b < 8; ++b) a[d][b] = 0.f;
#pragma unroll 2
        for (int k = 0; k < H; ++k) {
            float4 w = *reinterpret_cast<const float4*>(&g_Wd1t[k * D1C + d4]);
            const float4* ar = reinterpret_cast<const float4*>(&xh[k * NB + bb]);
            float4 a0 = ar[0], a1 = ar[1];
            float av[8] = {a0.x, a0.y, a0.z, a0.w, a1.x, a1.y, a1.z, a1.w};
#pragma unroll
            for (int b = 0; b < 8; ++b) {
                a[0][b] += w.x * av[b]; a[1][b] += w.y * av[b];
                a[2][b] += w.z * av[b]; a[3][b] += w.w * av[b];
            }
        }
#pragma unroll
        for (int d = 0; d < 4; ++d) {
            float bd = b_d1[d4 + d];
#pragma unroll
            for (int b = 0; b < 8; ++b) {
                float v = a[d][b] + bd;
                h0[(d4 + d) * NB + bb + b] = v > 0.f ? v : 0.f;
            }
        }
    }
    __syncthreads();

    // ---- dense2: [64] <- relu(h0 @ Wd2t + b_d2) -> h1 ----
    {
        int d4 = (tid >> 4) * 4;   // 0..60
        int bb = (tid & 15) * 4;   // 0..60
        float a[4][4];
#pragma unroll
        for (int d = 0; d < 4; ++d)
#pragma unroll
            for (int b = 0; b < 4; ++b) a[d][b] = 0.f;
#pragma unroll 2
        for (int k = 0; k < D1C; ++k) {
            float4 w  = *reinterpret_cast<const float4*>(&g_Wd2t[k * D2C + d4]);
            float4 av = *reinterpret_cast<const float4*>(&h0[k * NB + bb]);
            float avv[4] = {av.x, av.y, av.z, av.w};
#pragma unroll
            for (int b = 0; b < 4; ++b) {
                a[0][b] += w.x * avv[b]; a[1][b] += w.y * avv[b];
                a[2][b] += w.z * avv[b]; a[3][b] += w.w * avv[b];
            }
        }
#pragma unroll
        for (int d = 0; d < 4; ++d) {
            float bd = b_d2[d4 + d];
#pragma unroll
            for (int b = 0; b < 4; ++b) {
                float v = a[d][b] + bd;
                h1[(d4 + d) * NB + bb + b] = v > 0.f ? v : 0.f;
            }
        }
    }
    __syncthreads();

    // ---- dense3: out[b][30] = h1 @ W_d3^T + b_d3 ----
    if (tid < 240) {
        int d  = tid % NOUT;
        int bb = (tid / NOUT) * 8;
        float a[8];
#pragma unroll
        for (int b = 0; b < 8; ++b) a[b] = 0.f;
        for (int k = 0; k < D2C; ++k) {
            float w = W_d3[d * D2C + k];
#pragma unroll
            for (int b = 0; b < 8; ++b) a[b] += w * h1[k * NB + bb + b];
        }
        float bd = b_d3[d];
#pragma unroll
        for (int b = 0; b < 8; ++b)
            out[(long long)(bbase + bb + b) * NOUT + d] = a[b] + bd;
    }
}

// ---------------------------------------------------------------------------
extern "C" void kernel_launch(void* const* d_in, const int* in_sizes, int n_in,
                              void* d_out, int out_size)
{
    const float* x     = (const float*)d_in[0];
    const float* W_in  = (const float*)d_in[1];
    const float* b_in  = (const float*)d_in[2];
    const float* g_in  = (const float*)d_in[3];
    const float* be_in = (const float*)d_in[4];
    const float* Wih0  = (const float*)d_in[5];
    const float* Whh0  = (const float*)d_in[6];
    const float* bih0  = (const float*)d_in[7];
    const float* bhh0  = (const float*)d_in[8];
    const float* Wih1  = (const float*)d_in[9];
    const float* Whh1  = (const float*)d_in[10];
    const float* bih1  = (const float*)d_in[11];
    const float* bhh1  = (const float*)d_in[12];
    const float* g_ln  = (const float*)d_in[13];
    const float* be_ln = (const float*)d_in[14];
    const float* W_d1  = (const float*)d_in[15];
    const float* b_d1  = (const float*)d_in[16];
    const float* W_d2  = (const float*)d_in[17];
    const float* b_d2  = (const float*)d_in[18];
    const float* W_d3  = (const float*)d_in[19];
    const float* b_d3  = (const float*)d_in[20];
    float* out = (float*)d_out;

    prep_kernel<<<128, 256>>>(Wih0, Whh0, bih0, bhh0, Wih1, Whh1, bih1, bhh1,
                              W_d1, W_d2);

    size_t smem_bytes = (size_t)SM_TOTAL * sizeof(float);   // 176128 B
    cudaFuncSetAttribute(lstm_kernel,
                         cudaFuncAttributeMaxDynamicSharedMemorySize,
                         (int)smem_bytes);
    lstm_kernel<<<NCTA, NTHR, smem_bytes>>>(x, W_in, b_in, g_in, be_in,
                                            g_ln, be_ln, b_d1, b_d2, W_d3, b_d3,
                                            out);
}

// round 4
// speedup vs baseline: 1.0012x; 1.0012x over previous
#include <cuda_runtime.h>
#include <math.h>

// Problem constants
#define B_TOT 8192
#define T_STEPS 90
#define F_IN 7
#define H 128
#define G4 512      // 4*H
#define D1C 128
#define D2C 64
#define NOUT 30
#define NB 64       // batch rows per CTA
#define NCTA (B_TOT / NB)   // 128
#define NTHR 256

// ---------------------------------------------------------------------------
// Scratch: k-major transposed weights + fused biases (written by prep kernel
// each launch; __device__ globals to satisfy the no-alloc rule).
// ---------------------------------------------------------------------------
__device__ float g_Wt0[2 * H * G4];   // [k=256][j=512]: k<128 -> Wih0, else Whh0
__device__ float g_Wt1[2 * H * G4];
__device__ float g_Wd1t[H * D1C];     // [k=128][d=128]
__device__ float g_Wd2t[D1C * D2C];   // [k=128][d=64]
__device__ float g_bias0[G4];
__device__ float g_bias1[G4];

__global__ void prep_kernel(const float* __restrict__ Wih0, const float* __restrict__ Whh0,
                            const float* __restrict__ bih0, const float* __restrict__ bhh0,
                            const float* __restrict__ Wih1, const float* __restrict__ Whh1,
                            const float* __restrict__ bih1, const float* __restrict__ bhh1,
                            const float* __restrict__ Wd1,  const float* __restrict__ Wd2)
{
    int idx = blockIdx.x * blockDim.x + threadIdx.x;
    int stride = gridDim.x * blockDim.x;
    for (int i = idx; i < 2 * H * G4; i += stride) {
        int k = i / G4, j = i % G4;
        g_Wt0[i] = (k < H) ? Wih0[j * H + k] : Whh0[j * H + (k - H)];
        g_Wt1[i] = (k < H) ? Wih1[j * H + k] : Whh1[j * H + (k - H)];
    }
    for (int i = idx; i < H * D1C; i += stride) {
        int k = i / D1C, d = i % D1C;
        g_Wd1t[i] = Wd1[d * H + k];
    }
    for (int i = idx; i < D1C * D2C; i += stride) {
        int k = i / D2C, d = i % D2C;
        g_Wd2t[i] = Wd2[d * D1C + k];
    }
    for (int i = idx; i < G4; i += stride) {
        g_bias0[i] = bih0[i] + bhh0[i];
        g_bias1[i] = bih1[i] + bhh1[i];
    }
}

// ---------------------------------------------------------------------------
// f32x2 helpers (FFMA2 path — only reachable through PTX)
// ---------------------------------------------------------------------------
__device__ __forceinline__ unsigned long long splat2(float v) {
    unsigned long long r;
    asm("mov.b64 %0, {%1, %1};" : "=l"(r) : "f"(v));
    return r;
}
__device__ __forceinline__ unsigned long long pack2(float lo, float hi) {
    unsigned long long r;
    asm("mov.b64 %0, {%1, %2};" : "=l"(r) : "f"(lo), "f"(hi));
    return r;
}
__device__ __forceinline__ void unpack2(unsigned long long v, float& lo, float& hi) {
    asm("mov.b64 {%0, %1}, %2;" : "=f"(lo), "=f"(hi) : "l"(v));
}
__device__ __forceinline__ void ffma2(unsigned long long& d,
                                      unsigned long long a, unsigned long long b) {
    asm("fma.rn.f32x2 %0, %1, %2, %0;" : "+l"(d) : "l"(a), "l"(b));
}

__device__ __forceinline__ float sigf(float x) {
    return __fdividef(1.f, 1.f + __expf(-x));
}
__device__ __forceinline__ float tanh_fast(float x) {
    // tanh(x) = 2*sigmoid(2x) - 1
    return 2.f * sigf(2.f * x) - 1.f;
}

// One 128-k half of the gate GEMM. Wt: global k-major [128][512] (pre-offset),
// A: smem [128][64]. Accumulators packed over h-pairs.
__device__ __forceinline__ void gemm128(const float* __restrict__ Wt,
                                        const float* __restrict__ A,
                                        int h4, int b8,
                                        unsigned long long acc[4][2][8])
{
#pragma unroll 2
    for (int k = 0; k < H; ++k) {
        const float* wr = Wt + k * G4 + h4;
        ulonglong2 w0 = *reinterpret_cast<const ulonglong2*>(wr);
        ulonglong2 w1 = *reinterpret_cast<const ulonglong2*>(wr + 128);
        ulonglong2 w2 = *reinterpret_cast<const ulonglong2*>(wr + 256);
        ulonglong2 w3 = *reinterpret_cast<const ulonglong2*>(wr + 384);
        const float4* ar = reinterpret_cast<const float4*>(A + k * NB + b8);
        float4 a0 = ar[0];
        float4 a1 = ar[1];
        unsigned long long s[8];
        s[0] = splat2(a0.x); s[1] = splat2(a0.y); s[2] = splat2(a0.z); s[3] = splat2(a0.w);
        s[4] = splat2(a1.x); s[5] = splat2(a1.y); s[6] = splat2(a1.z); s[7] = splat2(a1.w);
#pragma unroll
        for (int b = 0; b < 8; ++b) {
            unsigned long long sv = s[b];
            ffma2(acc[0][0][b], w0.x, sv); ffma2(acc[0][1][b], w0.y, sv);
            ffma2(acc[1][0][b], w1.x, sv); ffma2(acc[1][1][b], w1.y, sv);
            ffma2(acc[2][0][b], w2.x, sv); ffma2(acc[2][1][b], w2.y, sv);
            ffma2(acc[3][0][b], w3.x, sv); ffma2(acc[3][1][b], w3.y, sv);
        }
    }
}

__device__ __forceinline__ void init_acc(unsigned long long acc[4][2][8],
                                         const float* __restrict__ bias, int h4)
{
#pragma unroll
    for (int g = 0; g < 4; ++g)
#pragma unroll
        for (int p = 0; p < 2; ++p) {
            unsigned long long bi = pack2(bias[g * H + h4 + 2 * p],
                                          bias[g * H + h4 + 2 * p + 1]);
#pragma unroll
            for (int b = 0; b < 8; ++b) acc[g][p][b] = bi;
        }
}

// Gate pointwise: c' = sig(f)*c + sig(i)*tanh(g); h = sig(o)*tanh(c')
__device__ __forceinline__ void pointwise(unsigned long long acc[4][2][8],
                                          float* __restrict__ cbuf,
                                          float* __restrict__ hbuf,
                                          int h4, int b8)
{
#pragma unroll
    for (int p = 0; p < 2; ++p) {
        int idx0 = (h4 + 2 * p) * NB + b8;
#pragma unroll
        for (int b = 0; b < 8; ++b) {
            float i0, i1, f0, f1, gg0, gg1, o0, o1;
            unpack2(acc[0][p][b], i0, i1);
            unpack2(acc[1][p][b], f0, f1);
            unpack2(acc[2][p][b], gg0, gg1);
            unpack2(acc[3][p][b], o0, o1);
            int idx = idx0 + b;
            float cp0 = cbuf[idx], cp1 = cbuf[idx + NB];
            float cn0 = sigf(f0) * cp0 + sigf(i0) * tanh_fast(gg0);
            float cn1 = sigf(f1) * cp1 + sigf(i1) * tanh_fast(gg1);
            cbuf[idx]      = cn0;
            cbuf[idx + NB] = cn1;
            hbuf[idx]      = sigf(o0) * tanh_fast(cn0);
            hbuf[idx + NB] = sigf(o1) * tanh_fast(cn1);
        }
    }
}

// SMEM layout (floats)
#define SM_XH    0          // [128][64]
#define SM_H0    8192
#define SM_H1    16384
#define SM_C0    24576
#define SM_C1    32768
#define SM_XROW  40960      // [64][8]
#define SM_WIN   41472      // [128][8]
#define SM_B0    42496      // [512]
#define SM_B1    43008      // [512]
#define SM_GIN   43520
#define SM_BEIN  43648
#define SM_GLN   43776
#define SM_BELN  43904
#define SM_TOTAL 44032      // floats -> 176128 bytes

__global__ void __launch_bounds__(NTHR, 1)
lstm_kernel(const float* __restrict__ x,
            const float* __restrict__ W_in, const float* __restrict__ b_in,
            const float* __restrict__ g_in, const float* __restrict__ be_in,
            const float* __restrict__ g_ln, const float* __restrict__ be_ln,
            const float* __restrict__ b_d1, const float* __restrict__ b_d2,
            const float* __restrict__ W_d3, const float* __restrict__ b_d3,
            float* __restrict__ out)
{
    extern __shared__ float sm[];
    float* xh   = sm + SM_XH;
    float* h0   = sm + SM_H0;
    float* h1   = sm + SM_H1;
    float* c0   = sm + SM_C0;
    float* c1   = sm + SM_C1;
    float* xrow = sm + SM_XROW;
    float* Wins = sm + SM_WIN;
    float* b0s  = sm + SM_B0;
    float* b1s  = sm + SM_B1;
    float* gins = sm + SM_GIN;
    float* beins= sm + SM_BEIN;
    float* glns = sm + SM_GLN;
    float* belns= sm + SM_BELN;

    const int tid   = threadIdx.x;
    const int cta   = blockIdx.x;
    const int bbase = cta * NB;

    // prologue: zero state, stage constants
    for (int i = tid; i < 32768; i += NTHR) sm[SM_H0 + i] = 0.f;   // h0,h1,c0,c1
    for (int i = tid; i < H * F_IN; i += NTHR) {
        int h = i / F_IN, f = i % F_IN;
        Wins[h * 8 + f] = W_in[i];
    }
    for (int i = tid; i < G4; i += NTHR) { b0s[i] = g_bias0[i]; b1s[i] = g_bias1[i]; }
    for (int i = tid; i < H; i += NTHR) {
        gins[i] = g_in[i]; beins[i] = be_in[i]; glns[i] = g_ln[i]; belns[i] = be_ln[i];
    }
    __syncthreads();

    const int h4 = (tid >> 3) * 4;   // hidden-tile base (0..124)
    const int b8 = (tid & 7) * 8;    // batch-tile base  (0..56)

    unsigned long long acc[4][2][8];

    for (int t = 0; t < T_STEPS; ++t) {
        // ---- input rows ----
        if (tid < NB) {
            const float* xr = x + ((long long)(bbase + tid) * T_STEPS + t) * F_IN;
#pragma unroll
            for (int f = 0; f < F_IN; ++f) xrow[tid * 8 + f] = xr[f];
        }
        __syncthreads();

        // ---- input projection: xh_raw[h][b] ----
        {
            int h  = tid >> 1;
            int bo = (tid & 1) * 32;
            float w[F_IN];
#pragma unroll
            for (int f = 0; f < F_IN; ++f) w[f] = Wins[h * 8 + f];
            float bi = b_in[h];
            for (int j = 0; j < 32; ++j) {
                int b = bo + j;
                float s = bi;
#pragma unroll
                for (int f = 0; f < F_IN; ++f) s += w[f] * xrow[b * 8 + f];
                xh[h * NB + b] = s;
            }
        }
        __syncthreads();

        // ---- LayerNorm over h (per batch row) ----
        if (tid < NB) {
            int b = tid;
            float s = 0.f, ss = 0.f;
            for (int h = 0; h < H; ++h) {
                float v = xh[h * NB + b];
                s += v; ss += v * v;
            }
            float mu = s * (1.f / H);
            float var = ss * (1.f / H) - mu * mu;
            float rs = rsqrtf(var + 1e-5f);
            for (int h = 0; h < H; ++h) {
                float v = xh[h * NB + b];
                xh[h * NB + b] = (v - mu) * rs * gins[h] + beins[h];
            }
        }
        __syncthreads();

        // ---- LSTM layer 0 ----
        init_acc(acc, b0s, h4);
        gemm128(g_Wt0,          xh, h4, b8, acc);
        gemm128(g_Wt0 + H * G4, h0, h4, b8, acc);
        __syncthreads();                       // all reads of h0 done
        pointwise(acc, c0, h0, h4, b8);
        __syncthreads();

        // ---- LSTM layer 1 ----
        init_acc(acc, b1s, h4);
        gemm128(g_Wt1,          h0, h4, b8, acc);
        gemm128(g_Wt1 + H * G4, h1, h4, b8, acc);
        __syncthreads();
        pointwise(acc, c1, h1, h4, b8);
        __syncthreads();
    }

    // ---- final LayerNorm on h1 -> xh ----
    if (tid < NB) {
        int b = tid;
        float s = 0.f, ss = 0.f;
        for (int h = 0; h < H; ++h) {
            float v = h1[h * NB + b];
            s += v; ss += v * v;
        }
        float mu = s * (1.f / H);
        float rs = rsqrtf(ss * (1.f / H) - mu * mu + 1e-5f);
        for (int h = 0; h < H; ++h) {
            float v = h1[h * NB + b];
            xh[h * NB + b] = (v - mu) * rs * glns[h] + belns[h];
        }
    }
    __syncthreads();

    // ---- dense1: [128] <- relu(xh @ Wd1t + b_d1) -> h0 ----
    {
        int d4 = (tid >> 3) * 4;
        int bb = (tid & 7) * 8;
        float a[4][8];
#pragma unroll
        for (int d = 0; d < 4; ++d)
#pragma unroll
            for (int b = 0; b < 8; ++b) a[d][b] = 0.f;
#pragma unroll 2
        for (int k = 0; k < H; ++k) {
            float4 w = *reinterpret_cast<const float4*>(&g_Wd1t[k * D1C + d4]);
            const float4* ar = reinterpret_cast<const float4*>(&xh[k * NB + bb]);
            float4 a0 = ar[0], a1 = ar[1];
            float av[8] = {a0.x, a0.y, a0.z, a0.w, a1.x, a1.y, a1.z, a1.w};
#pragma unroll
            for (int b = 0; b < 8; ++b) {
                a[0][b] += w.x * av[b]; a[1][b] += w.y * av[b];
                a[2][b] += w.z * av[b]; a[3][b] += w.w * av[b];
            }
        }
#pragma unroll
        for (int d = 0; d < 4; ++d) {
            float bd = b_d1[d4 + d];
#pragma unroll
            for (int b = 0; b < 8; ++b) {
                float v = a[d][b] + bd;
                h0[(d4 + d) * NB + bb + b] = v > 0.f ? v : 0.f;
            }
        }
    }
    __syncthreads();

    // ---- dense2: [64] <- relu(h0 @ Wd2t + b_d2) -> h1 ----
    {
        int d4 = (tid >> 4) * 4;   // 0..60
        int bb = (tid & 15) * 4;   // 0..60
        float a[4][4];
#pragma unroll
        for (int d = 0; d < 4; ++d)
#pragma unroll
            for (int b = 0; b < 4; ++b) a[d][b] = 0.f;
#pragma unroll 2
        for (int k = 0; k < D1C; ++k) {
            float4 w  = *reinterpret_cast<const float4*>(&g_Wd2t[k * D2C + d4]);
            float4 av = *reinterpret_cast<const float4*>(&h0[k * NB + bb]);
            float avv[4] = {av.x, av.y, av.z, av.w};
#pragma unroll
            for (int b = 0; b < 4; ++b) {
                a[0][b] += w.x * avv[b]; a[1][b] += w.y * avv[b];
                a[2][b] += w.z * avv[b]; a[3][b] += w.w * avv[b];
            }
        }
#pragma unroll
        for (int d = 0; d < 4; ++d) {
            float bd = b_d2[d4 + d];
#pragma unroll
            for (int b = 0; b < 4; ++b) {
                float v = a[d][b] + bd;
                h1[(d4 + d) * NB + bb + b] = v > 0.f ? v : 0.f;
            }
        }
    }
    __syncthreads();

    // ---- dense3: out[b][30] = h1 @ W_d3^T + b_d3 ----
    if (tid < 240) {
        int d  = tid % NOUT;
        int bb = (tid / NOUT) * 8;
        float a[8];
#pragma unroll
        for (int b = 0; b < 8; ++b) a[b] = 0.f;
        for (int k = 0; k < D2C; ++k) {
            float w = W_d3[d * D2C + k];
#pragma unroll
            for (int b = 0; b < 8; ++b) a[b] += w * h1[k * NB + bb + b];
        }
        float bd = b_d3[d];
#pragma unroll
        for (int b = 0; b < 8; ++b)
            out[(long long)(bbase + bb + b) * NOUT + d] = a[b] + bd;
    }
}

// ---------------------------------------------------------------------------
extern "C" void kernel_launch(void* const* d_in, const int* in_sizes, int n_in,
                              void* d_out, int out_size)
{
    const float* x     = (const float*)d_in[0];
    const float* W_in  = (const float*)d_in[1];
    const float* b_in  = (const float*)d_in[2];
    const float* g_in  = (const float*)d_in[3];
    const float* be_in = (const float*)d_in[4];
    const float* Wih0  = (const float*)d_in[5];
    const float* Whh0  = (const float*)d_in[6];
    const float* bih0  = (const float*)d_in[7];
    const float* bhh0  = (const float*)d_in[8];
    const float* Wih1  = (const float*)d_in[9];
    const float* Whh1  = (const float*)d_in[10];
    const float* bih1  = (const float*)d_in[11];
    const float* bhh1  = (const float*)d_in[12];
    const float* g_ln  = (const float*)d_in[13];
    const float* be_ln = (const float*)d_in[14];
    const float* W_d1  = (const float*)d_in[15];
    const float* b_d1  = (const float*)d_in[16];
    const float* W_d2  = (const float*)d_in[17];
    const float* b_d2  = (const float*)d_in[18];
    const float* W_d3  = (const float*)d_in[19];
    const float* b_d3  = (const float*)d_in[20];
    float* out = (float*)d_out;

    prep_kernel<<<128, 256>>>(Wih0, Whh0, bih0, bhh0, Wih1, Whh1, bih1, bhh1,
                              W_d1, W_d2);

    size_t smem_bytes = (size_t)SM_TOTAL * sizeof(float);   // 176128 B
    cudaFuncSetAttribute(lstm_kernel,
                         cudaFuncAttributeMaxDynamicSharedMemorySize,
                         (int)smem_bytes);
    lstm_kernel<<<NCTA, NTHR, smem_bytes>>>(x, W_in, b_in, g_in, be_in,
                                            g_ln, be_ln, b_d1, b_d2, W_d3, b_d3,
                                            out);
}

// round 7
// speedup vs baseline: 2.4886x; 2.4857x over previous
#include <cuda_runtime.h>
#include <cuda_bf16.h>
#include <cstdint>

#define B_TOT 8192
#define T_STEPS 90
#define H 128
#define NB 64
#define NCTA 128
#define NTHR 256
#define SKB 272u          // act row stride bytes (136 bf16)
#define CSTRIDE 68        // c buffer row stride (floats)

// ---- SMEM byte offsets ----
#define OFF_XA_HI 0u
#define OFF_XA_LO 17408u
#define OFF_H0_HI 34816u
#define OFF_H0_LO 52224u
#define OFF_H1_HI 69632u
#define OFF_H1_LO 87040u
#define OFF_SCR   104448u     // phase-A xproj [64][132] f32 / tail xhf [128][65] f32
#define OFF_C0    138240u     // [128][68] f32
#define OFF_C1    173056u
#define OFF_XROW  207872u     // [64][8] f32
#define OFF_WIN   209920u     // [128][8] f32 (slot7 = b_in)
#define OFF_LNP   214016u     // g_in,be_in,g_ln,be_ln (4x128 f32)
#define OFF_B0    216064u
#define OFF_B1    218112u
#define SMEM_TOTAL 220160u

// ---- device globals ----
// layout: [(L*8+w)][g][ks][hl][512B]  (strides 65536 / 16384 / 1024 / 512)
__device__ __align__(256) uint8_t g_Wpack[1048576];
__device__ float g_Wd1t[128 * 128];
__device__ float g_Wd2t[128 * 64];
__device__ float g_bias0[512];
__device__ float g_bias1[512];

__global__ void prep_kernel(const float* __restrict__ Wih0, const float* __restrict__ Whh0,
                            const float* __restrict__ bih0, const float* __restrict__ bhh0,
                            const float* __restrict__ Wih1, const float* __restrict__ Whh1,
                            const float* __restrict__ bih1, const float* __restrict__ bhh1,
                            const float* __restrict__ Wd1,  const float* __restrict__ Wd2)
{
    int idx = blockIdx.x * blockDim.x + threadIdx.x;
    int stride = gridDim.x * blockDim.x;
    // mma m16n8k16 a-fragment order with hi/lo split
    for (int i = idx; i < 524288; i += stride) {
        int e    = i & 1;
        int reg  = (i >> 1) & 3;
        int lane = (i >> 3) & 31;
        int hl   = (i >> 8) & 1;
        int ks   = (i >> 9) & 15;
        int g    = (i >> 13) & 3;
        int w    = (i >> 15) & 7;
        int L    = (i >> 18) & 1;
        int j = g * 128 + w * 16 + (lane >> 2) + (reg & 1) * 8;
        int k = ks * 16 + (lane & 3) * 2 + ((reg >> 1) & 1) * 8 + e;
        float v;
        if (L == 0) v = (k < H) ? Wih0[j * H + k] : Whh0[j * H + (k - H)];
        else        v = (k < H) ? Wih1[j * H + k] : Whh1[j * H + (k - H)];
        __nv_bfloat16 hi = __float2bfloat16(v);
        __nv_bfloat16 res = __float2bfloat16(v - __bfloat162float(hi));
        reinterpret_cast<__nv_bfloat16*>(g_Wpack)[i] = hl ? res : hi;
    }
    for (int i = idx; i < 128 * 128; i += stride) {
        int k = i >> 7, d = i & 127;
        g_Wd1t[i] = Wd1[d * H + k];
    }
    for (int i = idx; i < 128 * 64; i += stride) {
        int k = i >> 6, d = i & 63;
        g_Wd2t[i] = Wd2[d * 128 + k];
    }
    for (int i = idx; i < 512; i += stride) {
        g_bias0[i] = bih0[i] + bhh0[i];
        g_bias1[i] = bih1[i] + bhh1[i];
    }
}

// ---- helpers ----
__device__ __forceinline__ uint32_t smem_u32_of(const void* p) {
    uint32_t a;
    asm("{ .reg .u64 t; cvta.to.shared.u64 t, %1; cvt.u32.u64 %0, t; }" : "=r"(a) : "l"(p));
    return a;
}
__device__ __forceinline__ void ldmx4(uint32_t& r0, uint32_t& r1, uint32_t& r2, uint32_t& r3,
                                      uint32_t addr) {
    asm volatile("ldmatrix.sync.aligned.m8n8.x4.shared.b16 {%0,%1,%2,%3}, [%4];"
                 : "=r"(r0), "=r"(r1), "=r"(r2), "=r"(r3) : "r"(addr));
}
__device__ __forceinline__ void mma16816(float* c, uint4 a, uint32_t b0, uint32_t b1) {
    asm volatile("mma.sync.aligned.m16n8k16.row.col.f32.bf16.bf16.f32 "
                 "{%0,%1,%2,%3}, {%4,%5,%6,%7}, {%8,%9}, {%0,%1,%2,%3};"
                 : "+f"(c[0]), "+f"(c[1]), "+f"(c[2]), "+f"(c[3])
                 : "r"(a.x), "r"(a.y), "r"(a.z), "r"(a.w), "r"(b0), "r"(b1));
}
__device__ __forceinline__ float sigf(float x) {
    return __fdividef(1.f, 1.f + __expf(-x));
}
__device__ __forceinline__ float tanh_fast(float x) {
    return 2.f * sigf(2.f * x) - 1.f;
}
__device__ __forceinline__ void store_hilo(uint8_t* smb, uint32_t off_hi, uint32_t off_lo,
                                           uint32_t byte, float v) {
    __nv_bfloat16 hi = __float2bfloat16(v);
    __nv_bfloat16 lo = __float2bfloat16(v - __bfloat162float(hi));
    *reinterpret_cast<__nv_bfloat16*>(smb + off_hi + byte) = hi;
    *reinterpret_cast<__nv_bfloat16*>(smb + off_lo + byte) = lo;
}

__global__ void __launch_bounds__(NTHR, 1)
lstm_hmma_kernel(const float* __restrict__ x,
                 const float* __restrict__ W_in, const float* __restrict__ b_in,
                 const float* __restrict__ g_in, const float* __restrict__ be_in,
                 const float* __restrict__ g_ln, const float* __restrict__ be_ln,
                 const float* __restrict__ b_d1, const float* __restrict__ b_d2,
                 const float* __restrict__ W_d3, const float* __restrict__ b_d3,
                 float* __restrict__ out)
{
    extern __shared__ __align__(256) uint8_t smb[];
    const int tid  = threadIdx.x;
    const int w    = tid >> 5;
    const int lane = tid & 31;
    const int bbase = blockIdx.x * NB;

    uint32_t smbase = smem_u32_of(smb);
    float* scr  = reinterpret_cast<float*>(smb + OFF_SCR);
    float* xrow = reinterpret_cast<float*>(smb + OFF_XROW);
    float* wins = reinterpret_cast<float*>(smb + OFF_WIN);
    float* lnp  = reinterpret_cast<float*>(smb + OFF_LNP);
    float* b0s  = reinterpret_cast<float*>(smb + OFF_B0);
    float* b1s  = reinterpret_cast<float*>(smb + OFF_B1);

    // ---- prologue ----
    for (int i = tid; i < (6 * 17408) / 4; i += NTHR)
        reinterpret_cast<uint32_t*>(smb + OFF_XA_HI)[i] = 0u;            // all act buffers
    for (int i = tid; i < 2 * 128 * CSTRIDE; i += NTHR)
        reinterpret_cast<float*>(smb + OFF_C0)[i] = 0.f;
    for (int i = tid; i < H * 7; i += NTHR) {
        int h = i / 7, f = i % 7;
        wins[h * 8 + f] = W_in[i];
    }
    for (int i = tid; i < H; i += NTHR) {
        wins[i * 8 + 7] = b_in[i];
        lnp[i] = g_in[i]; lnp[128 + i] = be_in[i];
        lnp[256 + i] = g_ln[i]; lnp[384 + i] = be_ln[i];
    }
    for (int i = tid; i < 512; i += NTHR) { b0s[i] = g_bias0[i]; b1s[i] = g_bias1[i]; }
    __syncthreads();

    // ldmatrix lane offset within a 16-row (2 n-tile) group
    const int tI = lane >> 3, r = lane & 7;
    const uint32_t loffb = (uint32_t)((tI >> 1) * 8 + r) * SKB + (uint32_t)(tI & 1) * 16u;

    const int m0 = w * 16 + (lane >> 2);       // h row (second row = +8)
    const int nb0 = (lane & 3) * 2;

    for (int t = 0; t < T_STEPS; ++t) {
        // ================= phase A: x -> proj -> LN -> bf16 hi/lo xa =================
        if (tid < NB) {
            const float* xr = x + ((long long)(bbase + tid) * T_STEPS + t) * 7;
#pragma unroll
            for (int f = 0; f < 7; ++f) xrow[tid * 8 + f] = xr[f];
        }
        __syncthreads();
        {
            int b = tid >> 2, hq = tid & 3;
            float xv[7];
#pragma unroll
            for (int f = 0; f < 7; ++f) xv[f] = xrow[b * 8 + f];
            for (int h = hq * 32; h < hq * 32 + 32; ++h) {
                float s = wins[h * 8 + 7];
#pragma unroll
                for (int f = 0; f < 7; ++f) s += wins[h * 8 + f] * xv[f];
                scr[b * 132 + h] = s;
            }
        }
        __syncthreads();
        if (tid < NB) {
            int b = tid;
            float s = 0.f, ss = 0.f;
            for (int h = 0; h < H; ++h) {
                float v = scr[b * 132 + h];
                s += v; ss += v * v;
            }
            float mu = s * (1.f / H);
            float rs = rsqrtf(ss * (1.f / H) - mu * mu + 1e-5f);
            for (int h = 0; h < H; ++h) {
                float v = (scr[b * 132 + h] - mu) * rs * lnp[h] + lnp[128 + h];
                store_hilo(smb, OFF_XA_HI, OFF_XA_LO, (uint32_t)b * SKB + (uint32_t)h * 2u, v);
            }
        }
        __syncthreads();

        // ================= two LSTM layers =================
#pragma unroll 1
        for (int L = 0; L < 2; ++L) {
            const uint8_t* wbase = g_Wpack + (size_t)(L * 8 + w) * 65536;
            uint32_t in_hi  = smbase + (L == 0 ? OFF_XA_HI : OFF_H0_HI);
            uint32_t in_lo  = smbase + (L == 0 ? OFF_XA_LO : OFF_H0_LO);
            uint32_t re_hi  = smbase + (L == 0 ? OFF_H0_HI : OFF_H1_HI);
            uint32_t re_lo  = smbase + (L == 0 ? OFF_H0_LO : OFF_H1_LO);
            uint32_t out_hi = (L == 0 ? OFF_H0_HI : OFF_H1_HI);
            uint32_t out_lo = (L == 0 ? OFF_H0_LO : OFF_H1_LO);
            float* cbuf = reinterpret_cast<float*>(smb + (L == 0 ? OFF_C0 : OFF_C1));
            const float* bs = (L == 0) ? b0s : b1s;

            float acc[4][8][4];
#pragma unroll
            for (int g = 0; g < 4; ++g)
#pragma unroll
                for (int nt = 0; nt < 8; ++nt)
#pragma unroll
                    for (int q = 0; q < 4; ++q) acc[g][nt][q] = 0.f;

#pragma unroll 2
            for (int ks = 0; ks < 16; ++ks) {
                uint32_t bh_base = ((ks < 8) ? in_hi : re_hi) + (uint32_t)(ks & 7) * 32u + loffb;
                uint32_t bl_base = ((ks < 8) ? in_lo : re_lo) + (uint32_t)(ks & 7) * 32u + loffb;
                uint32_t bh[16], bl[16];
#pragma unroll
                for (int tp = 0; tp < 4; ++tp) {
                    ldmx4(bh[tp * 4], bh[tp * 4 + 1], bh[tp * 4 + 2], bh[tp * 4 + 3],
                          bh_base + (uint32_t)tp * 16u * SKB);
                    ldmx4(bl[tp * 4], bl[tp * 4 + 1], bl[tp * 4 + 2], bl[tp * 4 + 3],
                          bl_base + (uint32_t)tp * 16u * SKB);
                }
                const uint8_t* wk = wbase + ks * 1024 + lane * 16;
#pragma unroll
                for (int g = 0; g < 4; ++g) {
                    uint4 ahi = *reinterpret_cast<const uint4*>(wk + g * 16384);
                    uint4 alo = *reinterpret_cast<const uint4*>(wk + g * 16384 + 512);
#pragma unroll
                    for (int nt = 0; nt < 8; ++nt) {
                        mma16816(acc[g][nt], ahi, bh[nt * 2], bh[nt * 2 + 1]);
                        mma16816(acc[g][nt], alo, bh[nt * 2], bh[nt * 2 + 1]);
                        mma16816(acc[g][nt], ahi, bl[nt * 2], bl[nt * 2 + 1]);
                    }
                }
            }
            __syncthreads();   // all reads of rec buffers done before writes

            // ---- pointwise ----
            float bI[2] = { bs[m0],       bs[m0 + 8] };
            float bF[2] = { bs[128 + m0], bs[128 + m0 + 8] };
            float bG[2] = { bs[256 + m0], bs[256 + m0 + 8] };
            float bO[2] = { bs[384 + m0], bs[384 + m0 + 8] };
            int storef = (L == 1 && t == T_STEPS - 1);
#pragma unroll
            for (int nt = 0; nt < 8; ++nt) {
#pragma unroll
                for (int mi = 0; mi < 2; ++mi) {
                    int h = m0 + mi * 8;
#pragma unroll
                    for (int e = 0; e < 2; ++e) {
                        int n = nb0 + nt * 8 + e;
                        float pi = acc[0][nt][mi * 2 + e] + bI[mi];
                        float pf = acc[1][nt][mi * 2 + e] + bF[mi];
                        float pg = acc[2][nt][mi * 2 + e] + bG[mi];
                        float po = acc[3][nt][mi * 2 + e] + bO[mi];
                        float cp = cbuf[h * CSTRIDE + n];
                        float cn = sigf(pf) * cp + sigf(pi) * tanh_fast(pg);
                        cbuf[h * CSTRIDE + n] = cn;
                        float hv = sigf(po) * tanh_fast(cn);
                        store_hilo(smb, out_hi, out_lo,
                                   (uint32_t)n * SKB + (uint32_t)h * 2u, hv);
                        if (storef) scr[h * 65 + n] = hv;
                    }
                }
            }
            __syncthreads();
        }
    }

    // ================= tail: LN + dense head (fp32) =================
    if (tid < NB) {
        int b = tid;
        float s = 0.f, ss = 0.f;
        for (int h = 0; h < H; ++h) {
            float v = scr[h * 65 + b];
            s += v; ss += v * v;
        }
        float mu = s * (1.f / H);
        float rs = rsqrtf(ss * (1.f / H) - mu * mu + 1e-5f);
        for (int h = 0; h < H; ++h) {
            float v = scr[h * 65 + b];
            scr[h * 65 + b] = (v - mu) * rs * lnp[256 + h] + lnp[384 + h];
        }
    }
    __syncthreads();

    float* d1o = reinterpret_cast<float*>(smb + OFF_XA_HI);   // 32KB, act bufs dead
    float* d2o = reinterpret_cast<float*>(smb + OFF_H0_HI);   // 16KB

    // dense1
    {
        int d4 = (tid >> 3) * 4, bb = (tid & 7) * 8;
        float a[4][8];
#pragma unroll
        for (int d = 0; d < 4; ++d)
#pragma unroll
            for (int b = 0; b < 8; ++b) a[d][b] = 0.f;
        for (int k = 0; k < H; ++k) {
            float4 wv = *reinterpret_cast<const float4*>(&g_Wd1t[k * 128 + d4]);
            float av[8];
#pragma unroll
            for (int b = 0; b < 8; ++b) av[b] = scr[k * 65 + bb + b];
#pragma unroll
            for (int b = 0; b < 8; ++b) {
                a[0][b] += wv.x * av[b]; a[1][b] += wv.y * av[b];
                a[2][b] += wv.z * av[b]; a[3][b] += wv.w * av[b];
            }
        }
#pragma unroll
        for (int d = 0; d < 4; ++d) {
            float bd = b_d1[d4 + d];
#pragma unroll
            for (int b = 0; b < 8; ++b) {
                float v = a[d][b] + bd;
                d1o[(d4 + d) * 64 + bb + b] = v > 0.f ? v : 0.f;
            }
        }
    }
    __syncthreads();

    // dense2
    {
        int d4 = (tid >> 4) * 4, bb = (tid & 15) * 4;
        float a[4][4];
#pragma unroll
        for (int d = 0; d < 4; ++d)
#pragma unroll
            for (int b = 0; b < 4; ++b) a[d][b] = 0.f;
        for (int k = 0; k < 128; ++k) {
            float4 wv = *reinterpret_cast<const float4*>(&g_Wd2t[k * 64 + d4]);
            float av[4];
#pragma unroll
            for (int b = 0; b < 4; ++b) av[b] = d1o[k * 64 + bb + b];
#pragma unroll
            for (int b = 0; b < 4; ++b) {
                a[0][b] += wv.x * av[b]; a[1][b] += wv.y * av[b];
                a[2][b] += wv.z * av[b]; a[3][b] += wv.w * av[b];
            }
        }
#pragma unroll
        for (int d = 0; d < 4; ++d) {
            float bd = b_d2[d4 + d];
#pragma unroll
            for (int b = 0; b < 4; ++b) {
                float v = a[d][b] + bd;
                d2o[(d4 + d) * 64 + bb + b] = v > 0.f ? v : 0.f;
            }
        }
    }
    __syncthreads();

    // dense3
    if (tid < 240) {
        int d = tid % 30, bq = (tid / 30) * 8;
        float a[8];
#pragma unroll
        for (int b = 0; b < 8; ++b) a[b] = 0.f;
        for (int k = 0; k < 64; ++k) {
            float wv = W_d3[d * 64 + k];
#pragma unroll
            for (int b = 0; b < 8; ++b) a[b] += wv * d2o[k * 64 + bq + b];
        }
        float bd = b_d3[d];
#pragma unroll
        for (int b = 0; b < 8; ++b)
            out[(long long)(bbase + bq + b) * 30 + d] = a[b] + bd;
    }
}

// ---------------------------------------------------------------------------
extern "C" void kernel_launch(void* const* d_in, const int* in_sizes, int n_in,
                              void* d_out, int out_size)
{
    const float* x     = (const float*)d_in[0];
    const float* W_in  = (const float*)d_in[1];
    const float* b_in  = (const float*)d_in[2];
    const float* g_in  = (const float*)d_in[3];
    const float* be_in = (const float*)d_in[4];
    const float* Wih0  = (const float*)d_in[5];
    const float* Whh0  = (const float*)d_in[6];
    const float* bih0  = (const float*)d_in[7];
    const float* bhh0  = (const float*)d_in[8];
    const float* Wih1  = (const float*)d_in[9];
    const float* Whh1  = (const float*)d_in[10];
    const float* bih1  = (const float*)d_in[11];
    const float* bhh1  = (const float*)d_in[12];
    const float* g_ln  = (const float*)d_in[13];
    const float* be_ln = (const float*)d_in[14];
    const float* W_d1  = (const float*)d_in[15];
    const float* b_d1  = (const float*)d_in[16];
    const float* W_d2  = (const float*)d_in[17];
    const float* b_d2  = (const float*)d_in[18];
    const float* W_d3  = (const float*)d_in[19];
    const float* b_d3  = (const float*)d_in[20];
    float* out = (float*)d_out;

    prep_kernel<<<128, 256>>>(Wih0, Whh0, bih0, bhh0, Wih1, Whh1, bih1, bhh1,
                              W_d1, W_d2);

    cudaFuncSetAttribute(lstm_hmma_kernel,
                         cudaFuncAttributeMaxDynamicSharedMemorySize,
                         (int)SMEM_TOTAL);
    lstm_hmma_kernel<<<NCTA, NTHR, SMEM_TOTAL>>>(x, W_in, b_in, g_in, be_in,
                                                 g_ln, be_ln, b_d1, b_d2,
                                                 W_d3, b_d3, out);
}

// round 8
// speedup vs baseline: 2.5527x; 1.0257x over previous
#include <cuda_runtime.h>
#include <cuda_bf16.h>
#include <cstdint>

#define B_TOT 8192
#define T_STEPS 90
#define H 128
#define NB 64
#define NCTA 128
#define NTHR 512
#define SKB 272u          // act row stride bytes (136 bf16)
#define CSTRIDE 68        // c buffer row stride (floats)

// ---- SMEM byte offsets ----
#define OFF_XA_HI 0u
#define OFF_XA_LO 17408u
#define OFF_H0_HI 34816u
#define OFF_H0_LO 52224u
#define OFF_H1_HI 69632u
#define OFF_H1_LO 87040u
#define OFF_SCR   104448u     // phase-A xproj [64][132] f32 / tail xhf [128][65] f32
#define OFF_C0    138240u     // [128][68] f32
#define OFF_C1    173056u
#define OFF_XROW  207872u     // [64][8] f32 (also LN scratch)
#define OFF_WIN   209920u     // [128][8] f32 (slot7 = b_in)
#define OFF_LNP   214016u     // g_in,be_in,g_ln,be_ln (4x128 f32)
#define OFF_B0    216064u
#define OFF_B1    218112u
#define SMEM_TOTAL 220160u

// ---- device globals ----
// layout: [(L*8+w)][g][ks][hl][512B]  (strides 65536 / 16384 / 1024 / 512)
__device__ __align__(256) uint8_t g_Wpack[1048576];
__device__ float g_Wd1t[128 * 128];
__device__ float g_Wd2t[128 * 64];
__device__ float g_bias0[512];
__device__ float g_bias1[512];

__global__ void prep_kernel(const float* __restrict__ Wih0, const float* __restrict__ Whh0,
                            const float* __restrict__ bih0, const float* __restrict__ bhh0,
                            const float* __restrict__ Wih1, const float* __restrict__ Whh1,
                            const float* __restrict__ bih1, const float* __restrict__ bhh1,
                            const float* __restrict__ Wd1,  const float* __restrict__ Wd2)
{
    int idx = blockIdx.x * blockDim.x + threadIdx.x;
    int stride = gridDim.x * blockDim.x;
    // mma m16n8k16 a-fragment order with hi/lo split
    for (int i = idx; i < 524288; i += stride) {
        int e    = i & 1;
        int reg  = (i >> 1) & 3;
        int lane = (i >> 3) & 31;
        int hl   = (i >> 8) & 1;
        int ks   = (i >> 9) & 15;
        int g    = (i >> 13) & 3;
        int w    = (i >> 15) & 7;
        int L    = (i >> 18) & 1;
        int j = g * 128 + w * 16 + (lane >> 2) + (reg & 1) * 8;
        int k = ks * 16 + (lane & 3) * 2 + ((reg >> 1) & 1) * 8 + e;
        float v;
        if (L == 0) v = (k < H) ? Wih0[j * H + k] : Whh0[j * H + (k - H)];
        else        v = (k < H) ? Wih1[j * H + k] : Whh1[j * H + (k - H)];
        __nv_bfloat16 hi = __float2bfloat16(v);
        __nv_bfloat16 res = __float2bfloat16(v - __bfloat162float(hi));
        reinterpret_cast<__nv_bfloat16*>(g_Wpack)[i] = hl ? res : hi;
    }
    for (int i = idx; i < 128 * 128; i += stride) {
        int k = i >> 7, d = i & 127;
        g_Wd1t[i] = Wd1[d * H + k];
    }
    for (int i = idx; i < 128 * 64; i += stride) {
        int k = i >> 6, d = i & 63;
        g_Wd2t[i] = Wd2[d * 128 + k];
    }
    for (int i = idx; i < 512; i += stride) {
        g_bias0[i] = bih0[i] + bhh0[i];
        g_bias1[i] = bih1[i] + bhh1[i];
    }
}

// ---- helpers ----
__device__ __forceinline__ uint32_t smem_u32_of(const void* p) {
    uint32_t a;
    asm("{ .reg .u64 t; cvta.to.shared.u64 t, %1; cvt.u32.u64 %0, t; }" : "=r"(a) : "l"(p));
    return a;
}
__device__ __forceinline__ void ldmx4(uint32_t& r0, uint32_t& r1, uint32_t& r2, uint32_t& r3,
                                      uint32_t addr) {
    asm volatile("ldmatrix.sync.aligned.m8n8.x4.shared.b16 {%0,%1,%2,%3}, [%4];"
                 : "=r"(r0), "=r"(r1), "=r"(r2), "=r"(r3) : "r"(addr));
}
__device__ __forceinline__ void mma16816(float* c, uint4 a, uint32_t b0, uint32_t b1) {
    asm volatile("mma.sync.aligned.m16n8k16.row.col.f32.bf16.bf16.f32 "
                 "{%0,%1,%2,%3}, {%4,%5,%6,%7}, {%8,%9}, {%0,%1,%2,%3};"
                 : "+f"(c[0]), "+f"(c[1]), "+f"(c[2]), "+f"(c[3])
                 : "r"(a.x), "r"(a.y), "r"(a.z), "r"(a.w), "r"(b0), "r"(b1));
}
__device__ __forceinline__ float sigf(float x) {
    return __fdividef(1.f, 1.f + __expf(-x));
}
__device__ __forceinline__ float tanh_fast(float x) {
    return 2.f * sigf(2.f * x) - 1.f;
}
__device__ __forceinline__ void store_hilo(uint8_t* smb, uint32_t off_hi, uint32_t off_lo,
                                           uint32_t byte, float v) {
    __nv_bfloat16 hi = __float2bfloat16(v);
    __nv_bfloat16 lo = __float2bfloat16(v - __bfloat162float(hi));
    *reinterpret_cast<__nv_bfloat16*>(smb + off_hi + byte) = hi;
    *reinterpret_cast<__nv_bfloat16*>(smb + off_lo + byte) = lo;
}

__global__ void __launch_bounds__(NTHR, 1)
lstm_hmma_kernel(const float* __restrict__ x,
                 const float* __restrict__ W_in, const float* __restrict__ b_in,
                 const float* __restrict__ g_in, const float* __restrict__ be_in,
                 const float* __restrict__ g_ln, const float* __restrict__ be_ln,
                 const float* __restrict__ b_d1, const float* __restrict__ b_d2,
                 const float* __restrict__ W_d3, const float* __restrict__ b_d3,
                 float* __restrict__ out)
{
    extern __shared__ __align__(256) uint8_t smb[];
    const int tid   = threadIdx.x;
    const int w     = tid >> 5;
    const int wq    = w & 7;           // h-row group
    const int nhalf = w >> 3;          // n half (0: cols 0-31, 1: cols 32-63)
    const int lane  = tid & 31;
    const int bbase = blockIdx.x * NB;

    uint32_t smbase = smem_u32_of(smb);
    float* scr  = reinterpret_cast<float*>(smb + OFF_SCR);
    float* xrow = reinterpret_cast<float*>(smb + OFF_XROW);   // also LN scratch
    float* wins = reinterpret_cast<float*>(smb + OFF_WIN);
    float* lnp  = reinterpret_cast<float*>(smb + OFF_LNP);
    float* b0s  = reinterpret_cast<float*>(smb + OFF_B0);
    float* b1s  = reinterpret_cast<float*>(smb + OFF_B1);

    // ---- prologue ----
    for (int i = tid; i < (6 * 17408) / 4; i += NTHR)
        reinterpret_cast<uint32_t*>(smb + OFF_XA_HI)[i] = 0u;            // all act buffers
    for (int i = tid; i < 2 * 128 * CSTRIDE; i += NTHR)
        reinterpret_cast<float*>(smb + OFF_C0)[i] = 0.f;
    for (int i = tid; i < H * 7; i += NTHR) {
        int h = i / 7, f = i % 7;
        wins[h * 8 + f] = W_in[i];
    }
    for (int i = tid; i < H; i += NTHR) {
        wins[i * 8 + 7] = b_in[i];
        lnp[i] = g_in[i]; lnp[128 + i] = be_in[i];
        lnp[256 + i] = g_ln[i]; lnp[384 + i] = be_ln[i];
    }
    for (int i = tid; i < 512; i += NTHR) { b0s[i] = g_bias0[i]; b1s[i] = g_bias1[i]; }
    __syncthreads();

    // ldmatrix lane offset within a 16-row (2 n-tile) group
    const int tI = lane >> 3, r = lane & 7;
    const uint32_t loffb = (uint32_t)((tI >> 1) * 8 + r) * SKB + (uint32_t)(tI & 1) * 16u
                         + (uint32_t)nhalf * 32u * SKB;

    const int m0  = wq * 16 + (lane >> 2);     // h row (second row = +8)
    const int nb0 = (lane & 3) * 2;

    for (int t = 0; t < T_STEPS; ++t) {
        // ================= phase A: x -> proj -> LN -> bf16 hi/lo xa =================
        if (tid < NB) {
            const float* xr = x + ((long long)(bbase + tid) * T_STEPS + t) * 7;
#pragma unroll
            for (int f = 0; f < 7; ++f) xrow[tid * 8 + f] = xr[f];
        }
        __syncthreads();
        {
            int b = tid >> 3, hq = tid & 7;
            float xv[7];
#pragma unroll
            for (int f = 0; f < 7; ++f) xv[f] = xrow[b * 8 + f];
            for (int h = hq * 16; h < hq * 16 + 16; ++h) {
                float s = wins[h * 8 + 7];
#pragma unroll
                for (int f = 0; f < 7; ++f) s += wins[h * 8 + f] * xv[f];
                scr[b * 132 + h] = s;
            }
        }
        __syncthreads();
        // LN: stage 1 partial sums (xrow region reused as scratch)
        if (tid < 128) {
            int b = tid >> 1, hf = tid & 1;
            float s = 0.f, ss = 0.f;
            for (int h = hf * 64; h < hf * 64 + 64; ++h) {
                float v = scr[b * 132 + h];
                s += v; ss += v * v;
            }
            xrow[b * 2 + hf] = s;
            xrow[128 + b * 2 + hf] = ss;
        }
        __syncthreads();
        if (tid < NB) {
            int b = tid;
            float s  = xrow[b * 2] + xrow[b * 2 + 1];
            float ss = xrow[128 + b * 2] + xrow[128 + b * 2 + 1];
            float mu = s * (1.f / H);
            float rs = rsqrtf(ss * (1.f / H) - mu * mu + 1e-5f);
            xrow[256 + b] = mu;
            xrow[320 + b] = rs;
        }
        __syncthreads();
        for (int i = tid; i < NB * H; i += NTHR) {
            int b = i >> 7, h = i & 127;
            float v = (scr[b * 132 + h] - xrow[256 + b]) * xrow[320 + b] * lnp[h] + lnp[128 + h];
            store_hilo(smb, OFF_XA_HI, OFF_XA_LO, (uint32_t)b * SKB + (uint32_t)h * 2u, v);
        }
        __syncthreads();

        // ================= two LSTM layers =================
#pragma unroll 1
        for (int L = 0; L < 2; ++L) {
            const uint8_t* wbase = g_Wpack + (size_t)(L * 8 + wq) * 65536;
            uint32_t in_hi  = smbase + (L == 0 ? OFF_XA_HI : OFF_H0_HI);
            uint32_t in_lo  = smbase + (L == 0 ? OFF_XA_LO : OFF_H0_LO);
            uint32_t re_hi  = smbase + (L == 0 ? OFF_H0_HI : OFF_H1_HI);
            uint32_t re_lo  = smbase + (L == 0 ? OFF_H0_LO : OFF_H1_LO);
            uint32_t out_hi = (L == 0 ? OFF_H0_HI : OFF_H1_HI);
            uint32_t out_lo = (L == 0 ? OFF_H0_LO : OFF_H1_LO);
            float* cbuf = reinterpret_cast<float*>(smb + (L == 0 ? OFF_C0 : OFF_C1));
            const float* bs = (L == 0) ? b0s : b1s;

            float acc[4][4][4];
#pragma unroll
            for (int g = 0; g < 4; ++g)
#pragma unroll
                for (int nt = 0; nt < 4; ++nt)
#pragma unroll
                    for (int q = 0; q < 4; ++q) acc[g][nt][q] = 0.f;

#pragma unroll 2
            for (int ks = 0; ks < 16; ++ks) {
                uint32_t bh_base = ((ks < 8) ? in_hi : re_hi) + (uint32_t)(ks & 7) * 32u + loffb;
                uint32_t bl_base = ((ks < 8) ? in_lo : re_lo) + (uint32_t)(ks & 7) * 32u + loffb;
                uint32_t bh[8], bl[8];
#pragma unroll
                for (int tp = 0; tp < 2; ++tp) {
                    ldmx4(bh[tp * 4], bh[tp * 4 + 1], bh[tp * 4 + 2], bh[tp * 4 + 3],
                          bh_base + (uint32_t)tp * 16u * SKB);
                    ldmx4(bl[tp * 4], bl[tp * 4 + 1], bl[tp * 4 + 2], bl[tp * 4 + 3],
                          bl_base + (uint32_t)tp * 16u * SKB);
                }
                const uint8_t* wk = wbase + ks * 1024 + lane * 16;
#pragma unroll
                for (int g = 0; g < 4; ++g) {
                    uint4 ahi = *reinterpret_cast<const uint4*>(wk + g * 16384);
                    uint4 alo = *reinterpret_cast<const uint4*>(wk + g * 16384 + 512);
#pragma unroll
                    for (int nt = 0; nt < 4; ++nt) {
                        mma16816(acc[g][nt], ahi, bh[nt * 2], bh[nt * 2 + 1]);
                        mma16816(acc[g][nt], alo, bh[nt * 2], bh[nt * 2 + 1]);
                        mma16816(acc[g][nt], ahi, bl[nt * 2], bl[nt * 2 + 1]);
                    }
                }
            }
            __syncthreads();   // all reads of rec buffers done before writes

            // ---- pointwise ----
            float bI[2] = { bs[m0],       bs[m0 + 8] };
            float bF[2] = { bs[128 + m0], bs[128 + m0 + 8] };
            float bG[2] = { bs[256 + m0], bs[256 + m0 + 8] };
            float bO[2] = { bs[384 + m0], bs[384 + m0 + 8] };
            int storef = (L == 1 && t == T_STEPS - 1);
#pragma unroll
            for (int nt = 0; nt < 4; ++nt) {
#pragma unroll
                for (int mi = 0; mi < 2; ++mi) {
                    int h = m0 + mi * 8;
#pragma unroll
                    for (int e = 0; e < 2; ++e) {
                        int n = nhalf * 32 + nt * 8 + nb0 + e;
                        float pi = acc[0][nt][mi * 2 + e] + bI[mi];
                        float pf = acc[1][nt][mi * 2 + e] + bF[mi];
                        float pg = acc[2][nt][mi * 2 + e] + bG[mi];
                        float po = acc[3][nt][mi * 2 + e] + bO[mi];
                        float cp = cbuf[h * CSTRIDE + n];
                        float cn = sigf(pf) * cp + sigf(pi) * tanh_fast(pg);
                        cbuf[h * CSTRIDE + n] = cn;
                        float hv = sigf(po) * tanh_fast(cn);
                        store_hilo(smb, out_hi, out_lo,
                                   (uint32_t)n * SKB + (uint32_t)h * 2u, hv);
                        if (storef) scr[h * 65 + n] = hv;
                    }
                }
            }
            __syncthreads();
        }
    }

    // ================= tail: LN + dense head (fp32) =================
    if (tid < NB) {
        int b = tid;
        float s = 0.f, ss = 0.f;
        for (int h = 0; h < H; ++h) {
            float v = scr[h * 65 + b];
            s += v; ss += v * v;
        }
        float mu = s * (1.f / H);
        float rs = rsqrtf(ss * (1.f / H) - mu * mu + 1e-5f);
        for (int h = 0; h < H; ++h) {
            float v = scr[h * 65 + b];
            scr[h * 65 + b] = (v - mu) * rs * lnp[256 + h] + lnp[384 + h];
        }
    }
    __syncthreads();

    float* d1o = reinterpret_cast<float*>(smb + OFF_XA_HI);   // 32KB, act bufs dead
    float* d2o = reinterpret_cast<float*>(smb + OFF_H0_HI);   // 16KB

    // dense1
    if (tid < 256) {
        int d4 = (tid >> 3) * 4, bb = (tid & 7) * 8;
        float a[4][8];
#pragma unroll
        for (int d = 0; d < 4; ++d)
#pragma unroll
            for (int b = 0; b < 8; ++b) a[d][b] = 0.f;
        for (int k = 0; k < H; ++k) {
            float4 wv = *reinterpret_cast<const float4*>(&g_Wd1t[k * 128 + d4]);
            float av[8];
#pragma unroll
            for (int b = 0; b < 8; ++b) av[b] = scr[k * 65 + bb + b];
#pragma unroll
            for (int b = 0; b < 8; ++b) {
                a[0][b] += wv.x * av[b]; a[1][b] += wv.y * av[b];
                a[2][b] += wv.z * av[b]; a[3][b] += wv.w * av[b];
            }
        }
#pragma unroll
        for (int d = 0; d < 4; ++d) {
            float bd = b_d1[d4 + d];
#pragma unroll
            for (int b = 0; b < 8; ++b) {
                float v = a[d][b] + bd;
                d1o[(d4 + d) * 64 + bb + b] = v > 0.f ? v : 0.f;
            }
        }
    }
    __syncthreads();

    // dense2
    if (tid < 256) {
        int d4 = (tid >> 4) * 4, bb = (tid & 15) * 4;
        float a[4][4];
#pragma unroll
        for (int d = 0; d < 4; ++d)
#pragma unroll
            for (int b = 0; b < 4; ++b) a[d][b] = 0.f;
        for (int k = 0; k < 128; ++k) {
            float4 wv = *reinterpret_cast<const float4*>(&g_Wd2t[k * 64 + d4]);
            float av[4];
#pragma unroll
            for (int b = 0; b < 4; ++b) av[b] = d1o[k * 64 + bb + b];
#pragma unroll
            for (int b = 0; b < 4; ++b) {
                a[0][b] += wv.x * av[b]; a[1][b] += wv.y * av[b];
                a[2][b] += wv.z * av[b]; a[3][b] += wv.w * av[b];
            }
        }
#pragma unroll
        for (int d = 0; d < 4; ++d) {
            float bd = b_d2[d4 + d];
#pragma unroll
            for (int b = 0; b < 4; ++b) {
                float v = a[d][b] + bd;
                d2o[(d4 + d) * 64 + bb + b] = v > 0.f ? v : 0.f;
            }
        }
    }
    __syncthreads();

    // dense3
    if (tid < 240) {
        int d = tid % 30, bq = (tid / 30) * 8;
        float a[8];
#pragma unroll
        for (int b = 0; b < 8; ++b) a[b] = 0.f;
        for (int k = 0; k < 64; ++k) {
            float wv = W_d3[d * 64 + k];
#pragma unroll
            for (int b = 0; b < 8; ++b) a[b] += wv * d2o[k * 64 + bq + b];
        }
        float bd = b_d3[d];
#pragma unroll
        for (int b = 0; b < 8; ++b)
            out[(long long)(bbase + bq + b) * 30 + d] = a[b] + bd;
    }
}

// ---------------------------------------------------------------------------
extern "C" void kernel_launch(void* const* d_in, const int* in_sizes, int n_in,
                              void* d_out, int out_size)
{
    const float* x     = (const float*)d_in[0];
    const float* W_in  = (const float*)d_in[1];
    const float* b_in  = (const float*)d_in[2];
    const float* g_in  = (const float*)d_in[3];
    const float* be_in = (const float*)d_in[4];
    const float* Wih0  = (const float*)d_in[5];
    const float* Whh0  = (const float*)d_in[6];
    const float* bih0  = (const float*)d_in[7];
    const float* bhh0  = (const float*)d_in[8];
    const float* Wih1  = (const float*)d_in[9];
    const float* Whh1  = (const float*)d_in[10];
    const float* bih1  = (const float*)d_in[11];
    const float* bhh1  = (const float*)d_in[12];
    const float* g_ln  = (const float*)d_in[13];
    const float* be_ln = (const float*)d_in[14];
    const float* W_d1  = (const float*)d_in[15];
    const float* b_d1  = (const float*)d_in[16];
    const float* W_d2  = (const float*)d_in[17];
    const float* b_d2  = (const float*)d_in[18];
    const float* W_d3  = (const float*)d_in[19];
    const float* b_d3  = (const float*)d_in[20];
    float* out = (float*)d_out;

    prep_kernel<<<128, 256>>>(Wih0, Whh0, bih0, bhh0, Wih1, Whh1, bih1, bhh1,
                              W_d1, W_d2);

    cudaFuncSetAttribute(lstm_hmma_kernel,
                         cudaFuncAttributeMaxDynamicSharedMemorySize,
                         (int)SMEM_TOTAL);
    lstm_hmma_kernel<<<NCTA, NTHR, SMEM_TOTAL>>>(x, W_in, b_in, g_in, be_in,
                                                 g_ln, be_ln, b_d1, b_d2,
                                                 W_d3, b_d3, out);
}